// round 2
// baseline (speedup 1.0000x reference)
#include <cuda_runtime.h>

// AggregationFusion: out = silu(LN2(silu(LN1(concat(nodes, aggr_nodes[comps])) @ W1 + b1)) @ W2 + b2)
// N=100000, F=512, K=2F=1024. searchsorted(arange(M), comps) == comps.
//
// Round-1 baseline: fp32 SIMT tiled GEMMs with fused gather + LayerNorm (A-side)
// and fused bias+SiLU epilogue. 4 launches:
//   1) ln_stats<GATHER>   : per-row mean/rstd of concat(nodes, aggr_gather)
//   2) gemm_ln_silu<GATHER>: h2 = silu(LN1(A) @ W1 + b1)   -> __device__ scratch
//   3) ln_stats<!GATHER>  : per-row mean/rstd of h2
//   4) gemm_ln_silu<!GATHER>: out = silu(LN2(h2) @ W2 + b2)

#define FDIM 512
#define KDIM 1024
#define NMAX 100000

#define BM 128
#define BN 128
#define BK 16

// Scratch (allocation-free rule: __device__ globals)
__device__ float g_h2[(size_t)NMAX * KDIM];   // ~410 MB intermediate
__device__ float g_mu1[NMAX];
__device__ float g_rs1[NMAX];
__device__ float g_mu2[NMAX];
__device__ float g_rs2[NMAX];

// ---------------------------------------------------------------------------
// Per-row LayerNorm statistics: mean and rsqrt(var + eps) over 1024 elements.
// GATHER=true : row = concat(nodes[row][0:512], aggr_nodes[comps[row]][0:512])
// GATHER=false: row = A0[row][0:1024]
// One 128-thread block per row; each thread reads 2 float4 (8 floats).
// ---------------------------------------------------------------------------
template <bool GATHER>
__global__ void __launch_bounds__(128) ln_stats_kernel(
    const float* __restrict__ A0, const float* __restrict__ A1,
    const int* __restrict__ comps,
    float* __restrict__ mu_out, float* __restrict__ rs_out, int n)
{
    int row = blockIdx.x;
    if (row >= n) return;
    int t = threadIdx.x;

    const float4* p0;
    const float4* p1;
    if constexpr (GATHER) {
        p0 = reinterpret_cast<const float4*>(A0 + (size_t)row * FDIM);
        p1 = reinterpret_cast<const float4*>(A1 + (size_t)comps[row] * FDIM);
    } else {
        p0 = reinterpret_cast<const float4*>(A0 + (size_t)row * KDIM);
        p1 = p0 + 128;
    }
    float4 v0 = p0[t];
    float4 v1 = p1[t];
    float s = v0.x + v0.y + v0.z + v0.w + v1.x + v1.y + v1.z + v1.w;
    float q = v0.x * v0.x + v0.y * v0.y + v0.z * v0.z + v0.w * v0.w
            + v1.x * v1.x + v1.y * v1.y + v1.z * v1.z + v1.w * v1.w;

#pragma unroll
    for (int o = 16; o > 0; o >>= 1) {
        s += __shfl_xor_sync(0xffffffffu, s, o);
        q += __shfl_xor_sync(0xffffffffu, q, o);
    }
    __shared__ float ss[4], qs[4];
    if ((t & 31) == 0) { ss[t >> 5] = s; qs[t >> 5] = q; }
    __syncthreads();
    if (t == 0) {
        s = ss[0] + ss[1] + ss[2] + ss[3];
        q = qs[0] + qs[1] + qs[2] + qs[3];
        float mu = s * (1.0f / (float)KDIM);
        float var = q * (1.0f / (float)KDIM) - mu * mu;
        mu_out[row] = mu;
        rs_out[row] = rsqrtf(var + 1e-5f);
    }
}

// ---------------------------------------------------------------------------
// Fused GEMM: out[n, ncols] = silu( LN(A)[n,1024] @ W[1024,ncols] + bias )
// LN applied on-the-fly while staging A into shared memory (transposed).
// 256 threads, BM=BN=128, BK=16, 8x8 accumulators per thread.
// ---------------------------------------------------------------------------
template <bool GATHER>
__global__ void __launch_bounds__(256, 2) gemm_ln_silu_kernel(
    const float* __restrict__ A0, const float* __restrict__ A1,
    const int* __restrict__ comps,
    const float* __restrict__ mu, const float* __restrict__ rs,
    const float* __restrict__ lg, const float* __restrict__ lb,
    const float* __restrict__ W, const float* __restrict__ bias,
    float* __restrict__ out, int n, int ncols)
{
    __shared__ float As[BK][BM];   // transposed: As[k][m]
    __shared__ float Bs[BK][BN];   // row-major:  Bs[k][nj]

    const int tid  = threadIdx.x;
    const int row0 = blockIdx.y * BM;
    const int col0 = blockIdx.x * BN;

    // --- A-load assignment: thread owns (row = tid&127, k-half = tid>>7) ---
    const int arow  = tid & 127;
    const int ahalf = tid >> 7;           // 0 or 1 -> k offset 8*ahalf within BK
    const int rg    = row0 + arow;
    const int rc    = (rg < n) ? rg : (n - 1);   // clamp loads; stores guarded
    const float m_mu = mu[rc];
    const float m_rs = rs[rc];

    const float* rb0;  // source for k in [0,512)
    const float* rb1;  // source for k in [512,1024)
    if constexpr (GATHER) {
        rb0 = A0 + (size_t)rc * FDIM;
        rb1 = A1 + (size_t)comps[rc] * FDIM;
    } else {
        rb0 = A0 + (size_t)rc * KDIM;
        rb1 = rb0 + FDIM;
    }

    // --- compute assignment: 16x16 thread grid, 8x8 micro-tile ---
    const int tx = tid & 15;
    const int ty = tid >> 4;

    float acc[8][8];
#pragma unroll
    for (int i = 0; i < 8; i++)
#pragma unroll
        for (int j = 0; j < 8; j++) acc[i][j] = 0.0f;

    for (int k0 = 0; k0 < KDIM; k0 += BK) {
        // ---- stage A (with LN affine), transposed ----
        const int kg = k0 + ahalf * 8;   // 8-aligned; never straddles the 512 boundary
        const float* src = (kg < FDIM) ? (rb0 + kg) : (rb1 + (kg - FDIM));
        float4 a0  = *reinterpret_cast<const float4*>(src);
        float4 a1  = *reinterpret_cast<const float4*>(src + 4);
        float4 g0  = *reinterpret_cast<const float4*>(lg + kg);
        float4 g1  = *reinterpret_cast<const float4*>(lg + kg + 4);
        float4 c0  = *reinterpret_cast<const float4*>(lb + kg);
        float4 c1  = *reinterpret_cast<const float4*>(lb + kg + 4);
        const int ks = ahalf * 8;
        As[ks + 0][arow] = (a0.x - m_mu) * m_rs * g0.x + c0.x;
        As[ks + 1][arow] = (a0.y - m_mu) * m_rs * g0.y + c0.y;
        As[ks + 2][arow] = (a0.z - m_mu) * m_rs * g0.z + c0.z;
        As[ks + 3][arow] = (a0.w - m_mu) * m_rs * g0.w + c0.w;
        As[ks + 4][arow] = (a1.x - m_mu) * m_rs * g1.x + c1.x;
        As[ks + 5][arow] = (a1.y - m_mu) * m_rs * g1.y + c1.y;
        As[ks + 6][arow] = (a1.z - m_mu) * m_rs * g1.z + c1.z;
        As[ks + 7][arow] = (a1.w - m_mu) * m_rs * g1.w + c1.w;

        // ---- stage B: 16x128 floats = 512 float4, 2 per thread ----
#pragma unroll
        for (int i = 0; i < 2; i++) {
            int f  = tid + i * 256;
            int kr = f >> 5;            // 0..15
            int nc = (f & 31) << 2;     // 0..124 step 4
            *reinterpret_cast<float4*>(&Bs[kr][nc]) =
                *reinterpret_cast<const float4*>(W + (size_t)(k0 + kr) * ncols + col0 + nc);
        }
        __syncthreads();

        // ---- MACs ----
#pragma unroll
        for (int kk = 0; kk < BK; kk++) {
            float af[8], bf[8];
            *reinterpret_cast<float4*>(af)     = *reinterpret_cast<const float4*>(&As[kk][ty * 8]);
            *reinterpret_cast<float4*>(af + 4) = *reinterpret_cast<const float4*>(&As[kk][ty * 8 + 4]);
            *reinterpret_cast<float4*>(bf)     = *reinterpret_cast<const float4*>(&Bs[kk][tx * 8]);
            *reinterpret_cast<float4*>(bf + 4) = *reinterpret_cast<const float4*>(&Bs[kk][tx * 8 + 4]);
#pragma unroll
            for (int i = 0; i < 8; i++)
#pragma unroll
                for (int j = 0; j < 8; j++)
                    acc[i][j] = fmaf(af[i], bf[j], acc[i][j]);
        }
        __syncthreads();
    }

    // ---- epilogue: bias + SiLU, vectorized store ----
    float bb[8];
    *reinterpret_cast<float4*>(bb)     = *reinterpret_cast<const float4*>(bias + col0 + tx * 8);
    *reinterpret_cast<float4*>(bb + 4) = *reinterpret_cast<const float4*>(bias + col0 + tx * 8 + 4);
#pragma unroll
    for (int i = 0; i < 8; i++) {
        int r = row0 + ty * 8 + i;
        if (r < n) {
            float vals[8];
#pragma unroll
            for (int j = 0; j < 8; j++) {
                float c = acc[i][j] + bb[j];
                vals[j] = c / (1.0f + __expf(-c));   // silu; -0/inf behaves correctly
            }
            float* o = out + (size_t)r * ncols + col0 + tx * 8;
            *reinterpret_cast<float4*>(o)     = *reinterpret_cast<const float4*>(vals);
            *reinterpret_cast<float4*>(o + 4) = *reinterpret_cast<const float4*>(vals + 4);
        }
    }
}

// ---------------------------------------------------------------------------
// Input order (setup_inputs):
// 0 coords[N,3] 1 nodes[N,512] 2 comps[N](int32) 3 aggr_coords[M,3]
// 4 aggr_nodes[M,512] 5 aggr_comps[M] 6 ln1_g 7 ln1_b 8 W1[1024,1024]
// 9 b1 10 ln2_g 11 ln2_b 12 W2[1024,512] 13 b2
// ---------------------------------------------------------------------------
extern "C" void kernel_launch(void* const* d_in, const int* in_sizes, int n_in,
                              void* d_out, int out_size)
{
    const float* nodes      = (const float*)d_in[1];
    const int*   comps      = (const int*)  d_in[2];
    const float* aggr_nodes = (const float*)d_in[4];
    const float* ln1_g      = (const float*)d_in[6];
    const float* ln1_b      = (const float*)d_in[7];
    const float* W1         = (const float*)d_in[8];
    const float* b1         = (const float*)d_in[9];
    const float* ln2_g      = (const float*)d_in[10];
    const float* ln2_b      = (const float*)d_in[11];
    const float* W2         = (const float*)d_in[12];
    const float* b2         = (const float*)d_in[13];
    float*       out        = (float*)d_out;

    const int n = in_sizes[1] / FDIM;   // number of rows (100000)

    float *h2, *mu1, *rs1, *mu2, *rs2;
    cudaGetSymbolAddress((void**)&h2,  g_h2);
    cudaGetSymbolAddress((void**)&mu1, g_mu1);
    cudaGetSymbolAddress((void**)&rs1, g_rs1);
    cudaGetSymbolAddress((void**)&mu2, g_mu2);
    cudaGetSymbolAddress((void**)&rs2, g_rs2);

    const int rtiles = (n + BM - 1) / BM;

    // 1) LN1 stats over concat(nodes, gather(aggr_nodes, comps))
    ln_stats_kernel<true><<<n, 128>>>(nodes, aggr_nodes, comps, mu1, rs1, n);

    // 2) h2 = silu(LN1(A) @ W1 + b1)   [n, 1024]
    gemm_ln_silu_kernel<true><<<dim3(KDIM / BN, rtiles), 256>>>(
        nodes, aggr_nodes, comps, mu1, rs1, ln1_g, ln1_b, W1, b1, h2, n, KDIM);

    // 3) LN2 stats over h2
    ln_stats_kernel<false><<<n, 128>>>(h2, nullptr, nullptr, mu2, rs2, n);

    // 4) out = silu(LN2(h2) @ W2 + b2)   [n, 512]
    gemm_ln_silu_kernel<false><<<dim3(FDIM / BN, rtiles), 256>>>(
        h2, nullptr, nullptr, mu2, rs2, ln2_g, ln2_b, W2, b2, out, n, FDIM);
}

// round 5
// speedup vs baseline: 1.8648x; 1.8648x over previous
#include <cuda_runtime.h>
#include <cuda_bf16.h>
#include <stdint.h>

// out = silu(LN2(silu(LN1(concat(nodes, aggr[comps])) @ W1 + b1)) @ W2 + b2)
// bf16x3 split GEMMs on HMMA (mma.sync, sm_80 PTX -> works on plain sm_103 target),
// LayerNorm folded algebraically into GEMM epilogues:
//   LN(x)@W = rs*((x*g)@W) - rs*mu*(g@W) + (lnb@W + bias)

#define FDIM 512
#define KDIM 1024
#define NPAD 100096

#define BM 128
#define BN 128
#define KTOT 3072
#define NCHUNK 48
#define STAGES 3
#define TILE_BYTES (128 * 128)           // 16 KB per A or B stage tile
#define STAGE_BYTES (2 * TILE_BYTES)     // 32 KB
#define SMEM_TOTAL (STAGES * STAGE_BYTES) // 96 KB

// ---------------- device scratch (allocation-free rule) ----------------
__device__ __nv_bfloat16 g_A[(size_t)NPAD * 2048];     // [x*g1 hi | lo]
__device__ __nv_bfloat16 g_H[(size_t)NPAD * 2048];     // [h*g2 hi | lo]
__device__ __nv_bfloat16 g_W1p[(size_t)KDIM * KTOT];   // [c][k'] packed [hi;lo;hi]
__device__ __nv_bfloat16 g_W2p[(size_t)FDIM * KTOT];
__device__ float g_gW1[KDIM], g_eW1[KDIM];
__device__ float g_gW2[FDIM], g_eW2[FDIM];
__device__ float g_mu1[NPAD], g_rs1[NPAD], g_mu2[NPAD], g_rs2[NPAD];
__device__ float g_rsum[NPAD], g_rsq[NPAD];

// ---------------- PTX helpers (all baseline sm_80-era; no 'a' features) ----
__device__ __forceinline__ uint32_t smem_u32(const void* p) {
    uint32_t a;
    asm("{ .reg .u64 t; cvta.to.shared.u64 t, %1; cvt.u32.u64 %0, t; }" : "=r"(a) : "l"(p));
    return a;
}
__device__ __forceinline__ void cp16(uint32_t dst, const void* src) {
    asm volatile("cp.async.cg.shared.global [%0], [%1], 16;" :: "r"(dst), "l"(src));
}
#define SWZ(o) ((o) ^ (((o) >> 3) & 0x70))

__device__ __forceinline__ void ldsm4(uint32_t* r, uint32_t addr) {
    asm volatile("ldmatrix.sync.aligned.m8n8.x4.shared.b16 {%0,%1,%2,%3}, [%4];"
                 : "=r"(r[0]), "=r"(r[1]), "=r"(r[2]), "=r"(r[3]) : "r"(addr));
}
__device__ __forceinline__ void mma16816(float* c, const uint32_t* a, const uint32_t* b) {
    asm volatile(
        "mma.sync.aligned.m16n8k16.row.col.f32.bf16.bf16.f32 "
        "{%0,%1,%2,%3}, {%4,%5,%6,%7}, {%8,%9}, {%0,%1,%2,%3};"
        : "+f"(c[0]), "+f"(c[1]), "+f"(c[2]), "+f"(c[3])
        : "r"(a[0]), "r"(a[1]), "r"(a[2]), "r"(a[3]), "r"(b[0]), "r"(b[1]));
}

// ---------------- precompute: pack W -> [hi; lo; hi], transposed to [c][k'] --
__global__ void __launch_bounds__(256) pack_kernel(const float* __restrict__ W,
                                                   __nv_bfloat16* __restrict__ Wp, int C) {
    size_t total = (size_t)C * KTOT;
    for (size_t idx = (size_t)blockIdx.x * 256 + threadIdx.x; idx < total;
         idx += (size_t)gridDim.x * 256) {
        int c  = (int)(idx / KTOT);
        int kp = (int)(idx % KTOT);
        int k  = kp & 1023;
        float v = W[(size_t)k * C + c];
        __nv_bfloat16 hi = __float2bfloat16(v);
        Wp[idx] = (kp >= 1024 && kp < 2048)
                      ? __float2bfloat16(v - __bfloat162float(hi)) : hi;
    }
}

// gW[c] = sum_k g[k] W[k][c];  eW[c] = sum_k lnb[k] W[k][c] + bias[c]
__global__ void __launch_bounds__(256) gemv_kernel(const float* __restrict__ W,
    const float* __restrict__ g, const float* __restrict__ lnb,
    const float* __restrict__ bias, float* __restrict__ gW, float* __restrict__ eW, int C) {
    int c = blockIdx.x;
    float sg = 0.f, sb = 0.f;
    for (int k = threadIdx.x; k < KDIM; k += 256) {
        float w = W[(size_t)k * C + c];
        sg += g[k] * w; sb += lnb[k] * w;
    }
    __shared__ float ra[256], rb[256];
    ra[threadIdx.x] = sg; rb[threadIdx.x] = sb; __syncthreads();
    for (int o = 128; o > 0; o >>= 1) {
        if (threadIdx.x < o) { ra[threadIdx.x] += ra[threadIdx.x + o]; rb[threadIdx.x] += rb[threadIdx.x + o]; }
        __syncthreads();
    }
    if (threadIdx.x == 0) { gW[c] = ra[0]; eW[c] = rb[0] + bias[c]; }
}

// ---------------- stage 1: LN1 stats + bf16 split of x*g1 ----------------
__global__ void __launch_bounds__(128) s1_kernel(
    const float* __restrict__ nodes, const float* __restrict__ aggr,
    const int* __restrict__ comps, const float* __restrict__ g1,
    __nv_bfloat16* __restrict__ Aout, float* __restrict__ mu1, float* __restrict__ rs1,
    float* __restrict__ rsum, float* __restrict__ rsq, int n) {
    int row = blockIdx.x;
    if (row >= n) return;
    int t = threadIdx.x;
    const float4* p0 = (const float4*)(nodes + (size_t)row * FDIM);
    const float4* p1 = (const float4*)(aggr + (size_t)comps[row] * FDIM);
    float4 v0 = p0[t], v1 = p1[t];
    float s = v0.x + v0.y + v0.z + v0.w + v1.x + v1.y + v1.z + v1.w;
    float q = v0.x * v0.x + v0.y * v0.y + v0.z * v0.z + v0.w * v0.w
            + v1.x * v1.x + v1.y * v1.y + v1.z * v1.z + v1.w * v1.w;
#pragma unroll
    for (int o = 16; o > 0; o >>= 1) {
        s += __shfl_xor_sync(0xffffffffu, s, o);
        q += __shfl_xor_sync(0xffffffffu, q, o);
    }
    __shared__ float ss[4], qs[4];
    if ((t & 31) == 0) { ss[t >> 5] = s; qs[t >> 5] = q; }
    __syncthreads();
    if (t == 0) {
        s = ss[0] + ss[1] + ss[2] + ss[3];
        q = qs[0] + qs[1] + qs[2] + qs[3];
        float mu = s * (1.0f / 1024.0f);
        float var = q * (1.0f / 1024.0f) - mu * mu;
        mu1[row] = mu; rs1[row] = rsqrtf(var + 1e-5f);
        rsum[row] = 0.f; rsq[row] = 0.f;
    }
    const float4 gA = ((const float4*)g1)[t];
    const float4 gB = ((const float4*)g1)[128 + t];
    float xs[8] = { v0.x * gA.x, v0.y * gA.y, v0.z * gA.z, v0.w * gA.w,
                    v1.x * gB.x, v1.y * gB.y, v1.z * gB.z, v1.w * gB.w };
    __nv_bfloat16* base = Aout + (size_t)row * 2048;
#pragma unroll
    for (int j = 0; j < 8; j++) {
        int col = (j < 4) ? (4 * t + j) : (512 + 4 * t + (j - 4));
        __nv_bfloat16 hi = __float2bfloat16(xs[j]);
        base[col] = hi;
        base[1024 + col] = __float2bfloat16(xs[j] - __bfloat162float(hi));
    }
}

__global__ void __launch_bounds__(256) stat2_kernel(const float* __restrict__ rsum,
    const float* __restrict__ rsq, float* __restrict__ mu2, float* __restrict__ rs2, int n) {
    int i = blockIdx.x * 256 + threadIdx.x;
    if (i >= n) return;
    float mu = rsum[i] * (1.0f / 1024.0f);
    float var = rsq[i] * (1.0f / 1024.0f) - mu * mu;
    mu2[i] = mu; rs2[i] = rsqrtf(var + 1e-5f);
}

// ---------------- HMMA GEMM, K' = 3072, BM=BN=128, 8 warps -----------------
// warp (wm = wid&3, wn = wid>>2) computes 32 (m) x 64 (n); mma m16n8k16 bf16.
template <int LAYER>
__global__ void __launch_bounds__(256, 2) gemm_kernel(
    const __nv_bfloat16* __restrict__ Ain, const __nv_bfloat16* __restrict__ Bp,
    const float* __restrict__ mu, const float* __restrict__ rs,
    const float* __restrict__ gW, const float* __restrict__ eW,
    const float* __restrict__ g2,
    __nv_bfloat16* __restrict__ Hout, float* __restrict__ outp,
    float* __restrict__ rsum, float* __restrict__ rsq, int n, int ncols)
{
    extern __shared__ char smem[];
    uint32_t sb = smem_u32(smem);
    const int tid  = threadIdx.x;
    const int wid  = tid >> 5;
    const int lane = tid & 31;
    const int wm = wid & 3, wn = wid >> 2;
    const int row0 = blockIdx.y * BM;
    const int col0 = blockIdx.x * BN;

    float acc[2][8][4];
#pragma unroll
    for (int mt = 0; mt < 2; mt++)
#pragma unroll
        for (int nt = 0; nt < 8; nt++)
#pragma unroll
            for (int i = 0; i < 4; i++) acc[mt][nt][i] = 0.f;

    auto load_chunk = [&](int c) {
        int st = c % STAGES;
        uint32_t abase = sb + st * STAGE_BYTES;
        uint32_t bbase = abase + TILE_BYTES;
        int acol = ((c & 15) << 6) + ((c >= 32) ? 1024 : 0);
        int bcol = c << 6;
#pragma unroll
        for (int i = 0; i < 4; i++) {
            int v = tid + i * 256, r = v >> 3, cc = v & 7;
            int rg = row0 + r; if (rg >= n) rg = n - 1;
            cp16(abase + SWZ(r * 128 + cc * 16), Ain + (size_t)rg * 2048 + acol + cc * 8);
        }
#pragma unroll
        for (int i = 0; i < 4; i++) {
            int v = tid + i * 256, r = v >> 3, cc = v & 7;
            cp16(bbase + SWZ(r * 128 + cc * 16), Bp + (size_t)(col0 + r) * KTOT + bcol + cc * 8);
        }
        asm volatile("cp.async.commit_group;" ::: "memory");
    };

    load_chunk(0);
    load_chunk(1);

    const int a_row = wm * 32 + (lane & 15);   // + mt*16
    const int b_row = wn * 64 + (lane & 15);   // + nt16*16
    const int k8    = (lane >> 4) * 8;         // element offset within 16-col step

    for (int c = 0; c < NCHUNK; c++) {
        if (c + 2 < NCHUNK) asm volatile("cp.async.wait_group 1;" ::: "memory");
        else                asm volatile("cp.async.wait_group 0;" ::: "memory");
        __syncthreads();
        if (c + 2 < NCHUNK) load_chunk(c + 2);

        uint32_t abase = sb + (c % STAGES) * STAGE_BYTES;
        uint32_t bbase = abase + TILE_BYTES;
#pragma unroll
        for (int ks = 0; ks < 4; ks++) {
            uint32_t a[2][4], b[8][2];
#pragma unroll
            for (int mt = 0; mt < 2; mt++)
                ldsm4(a[mt], abase + SWZ((a_row + mt * 16) * 128 + (ks * 16 + k8) * 2));
#pragma unroll
            for (int nt16 = 0; nt16 < 4; nt16++) {
                uint32_t r[4];
                ldsm4(r, bbase + SWZ((b_row + nt16 * 16) * 128 + (ks * 16 + k8) * 2));
                b[2 * nt16 + 0][0] = r[0]; b[2 * nt16 + 0][1] = r[2];
                b[2 * nt16 + 1][0] = r[1]; b[2 * nt16 + 1][1] = r[3];
            }
#pragma unroll
            for (int mt = 0; mt < 2; mt++)
#pragma unroll
                for (int nt = 0; nt < 8; nt++)
                    mma16816(acc[mt][nt], a[mt], b[nt]);
        }
        __syncthreads();
    }

    // ---- epilogue ----
    const int qid   = lane >> 2;   // row within 8
    const int qlane = lane & 3;    // column pair selector

    // per-thread column constants (16 columns: 8 n-tiles x 2)
    float gwv[8][2], ewv[8][2], g2v[8][2];
#pragma unroll
    for (int nt = 0; nt < 8; nt++) {
        int colb = col0 + wn * 64 + nt * 8 + qlane * 2;
        gwv[nt][0] = __ldg(gW + colb);     gwv[nt][1] = __ldg(gW + colb + 1);
        ewv[nt][0] = __ldg(eW + colb);     ewv[nt][1] = __ldg(eW + colb + 1);
        if (LAYER == 1) { g2v[nt][0] = __ldg(g2 + colb); g2v[nt][1] = __ldg(g2 + colb + 1); }
    }

#pragma unroll
    for (int mt = 0; mt < 2; mt++) {
#pragma unroll
        for (int half = 0; half < 2; half++) {
            int row = row0 + wm * 32 + mt * 16 + qid + half * 8;
            bool valid = row < n;
            int rc = valid ? row : 0;
            float m_mu = mu[rc], m_rs = rs[rc];
            float ssum = 0.f, sq = 0.f;
#pragma unroll
            for (int nt = 0; nt < 8; nt++) {
                float c0 = m_rs * (acc[mt][nt][half * 2 + 0] - m_mu * gwv[nt][0]) + ewv[nt][0];
                float c1 = m_rs * (acc[mt][nt][half * 2 + 1] - m_mu * gwv[nt][1]) + ewv[nt][1];
                float h0 = c0 / (1.f + __expf(-c0));
                float h1 = c1 / (1.f + __expf(-c1));
                int colb = col0 + wn * 64 + nt * 8 + qlane * 2;
                if (LAYER == 1) {
                    ssum += h0 + h1; sq += h0 * h0 + h1 * h1;
                    float t0 = h0 * g2v[nt][0], t1 = h1 * g2v[nt][1];
                    __nv_bfloat16 hi0 = __float2bfloat16(t0);
                    __nv_bfloat16 hi1 = __float2bfloat16(t1);
                    __nv_bfloat162 hp; hp.x = hi0; hp.y = hi1;
                    __nv_bfloat162 lp;
                    lp.x = __float2bfloat16(t0 - __bfloat162float(hi0));
                    lp.y = __float2bfloat16(t1 - __bfloat162float(hi1));
                    if (valid) {
                        *(__nv_bfloat162*)(Hout + (size_t)row * 2048 + colb)        = hp;
                        *(__nv_bfloat162*)(Hout + (size_t)row * 2048 + 1024 + colb) = lp;
                    }
                } else {
                    if (valid) {
                        float2 v; v.x = h0; v.y = h1;
                        *(float2*)(outp + (size_t)row * ncols + colb) = v;
                    }
                }
            }
            if (LAYER == 1) {
                ssum += __shfl_xor_sync(0xffffffffu, ssum, 1);
                ssum += __shfl_xor_sync(0xffffffffu, ssum, 2);
                sq   += __shfl_xor_sync(0xffffffffu, sq, 1);
                sq   += __shfl_xor_sync(0xffffffffu, sq, 2);
                if (qlane == 0 && valid) {
                    atomicAdd(&rsum[row], ssum);
                    atomicAdd(&rsq[row], sq);
                }
            }
        }
    }
}

// ---------------------------------------------------------------------------
extern "C" void kernel_launch(void* const* d_in, const int* in_sizes, int n_in,
                              void* d_out, int out_size) {
    const float* nodes      = (const float*)d_in[1];
    const int*   comps      = (const int*)  d_in[2];
    const float* aggr_nodes = (const float*)d_in[4];
    const float* ln1_g      = (const float*)d_in[6];
    const float* ln1_b      = (const float*)d_in[7];
    const float* W1         = (const float*)d_in[8];
    const float* b1         = (const float*)d_in[9];
    const float* ln2_g      = (const float*)d_in[10];
    const float* ln2_b      = (const float*)d_in[11];
    const float* W2         = (const float*)d_in[12];
    const float* b2         = (const float*)d_in[13];
    float*       out        = (float*)d_out;

    const int n = in_sizes[1] / FDIM;

    __nv_bfloat16 *A, *H, *W1p, *W2p;
    float *gW1, *eW1, *gW2, *eW2, *mu1, *rs1, *mu2, *rs2, *rsum, *rsq;
    cudaGetSymbolAddress((void**)&A,    g_A);
    cudaGetSymbolAddress((void**)&H,    g_H);
    cudaGetSymbolAddress((void**)&W1p,  g_W1p);
    cudaGetSymbolAddress((void**)&W2p,  g_W2p);
    cudaGetSymbolAddress((void**)&gW1,  g_gW1);
    cudaGetSymbolAddress((void**)&eW1,  g_eW1);
    cudaGetSymbolAddress((void**)&gW2,  g_gW2);
    cudaGetSymbolAddress((void**)&eW2,  g_eW2);
    cudaGetSymbolAddress((void**)&mu1,  g_mu1);
    cudaGetSymbolAddress((void**)&rs1,  g_rs1);
    cudaGetSymbolAddress((void**)&mu2,  g_mu2);
    cudaGetSymbolAddress((void**)&rs2,  g_rs2);
    cudaGetSymbolAddress((void**)&rsum, g_rsum);
    cudaGetSymbolAddress((void**)&rsq,  g_rsq);

    cudaFuncSetAttribute(gemm_kernel<1>, cudaFuncAttributeMaxDynamicSharedMemorySize, SMEM_TOTAL);
    cudaFuncSetAttribute(gemm_kernel<2>, cudaFuncAttributeMaxDynamicSharedMemorySize, SMEM_TOTAL);

    const int rtiles = (n + BM - 1) / BM;

    // precompute (deterministic, every call)
    pack_kernel<<<2048, 256>>>(W1, W1p, KDIM);
    pack_kernel<<<2048, 256>>>(W2, W2p, FDIM);
    gemv_kernel<<<KDIM, 256>>>(W1, ln1_g, ln1_b, b1, gW1, eW1, KDIM);
    gemv_kernel<<<FDIM, 256>>>(W2, ln2_g, ln2_b, b2, gW2, eW2, FDIM);

    // stage 1: LN1 stats + bf16 split of x*g1 (also zeroes LN2 accumulators)
    s1_kernel<<<n, 128>>>(nodes, aggr_nodes, comps, ln1_g, A, mu1, rs1, rsum, rsq, n);

    // GEMM1: h-split + LN2 partial sums
    gemm_kernel<1><<<dim3(KDIM / BN, rtiles), 256, SMEM_TOTAL>>>(
        A, W1p, mu1, rs1, gW1, eW1, ln2_g, H, nullptr, rsum, rsq, n, KDIM);

    // LN2 stats
    stat2_kernel<<<(n + 255) / 256, 256>>>(rsum, rsq, mu2, rs2, n);

    // GEMM2 -> out
    gemm_kernel<2><<<dim3(FDIM / BN, rtiles), 256, SMEM_TOTAL>>>(
        H, W2p, mu2, rs2, gW2, eW2, nullptr, nullptr, out, nullptr, nullptr, n, FDIM);
}

// round 6
// speedup vs baseline: 4.3348x; 2.3246x over previous
#include <cuda_runtime.h>
#include <cuda_fp16.h>
#include <stdint.h>

// out = silu(LN2(silu(LN1(concat(nodes, aggr[comps])) @ W1 + b1)) @ W2 + b2)
// fp16 2-term split GEMMs on HMMA (mma.sync m16n8k16.f16):
//   A rounded to fp16 once; W' = diag(ln_g)*W split into [W'hi; W'lo] (fp16 pair).
//   C = A_f16 @ W'hi + A_f16 @ W'lo   (dropped term (A-Af16)*W' ~ 2^-12 rel)
// LayerNorm folded algebraically: LN(x)@W = rs*((x*g)@W) - rs*mu*(g@W) + (lnb@W + b)

#define FDIM 512
#define KDIM 1024
#define NPAD 100096

#define BM 128
#define BN 128
#define KTOT 2048
#define NCHUNK 32
#define STAGES 3
#define TILE_BYTES (128 * 128)            // 16 KB per A or B stage tile
#define STAGE_BYTES (2 * TILE_BYTES)      // 32 KB
#define SMEM_TOTAL (STAGES * STAGE_BYTES) // 96 KB

// ---------------- device scratch (allocation-free rule) ----------------
__device__ __half g_A[(size_t)NPAD * 1024];      // fp16(x) concat
__device__ __half g_H[(size_t)NPAD * 1024];      // fp16(silu(.))
__device__ __half g_W1p[(size_t)KDIM * KTOT];    // [c][k'] = [g1*W1 hi ; lo]
__device__ __half g_W2p[(size_t)FDIM * KTOT];    // [c][k'] = [g2*W2 hi ; lo]
__device__ float g_gW1[KDIM], g_eW1[KDIM];
__device__ float g_gW2[FDIM], g_eW2[FDIM];
__device__ float g_mu1[NPAD], g_rs1[NPAD], g_mu2[NPAD], g_rs2[NPAD];
__device__ float g_rsum[NPAD], g_rsq[NPAD];

// ---------------- PTX helpers (baseline sm_80-era; safe on plain sm_103) ---
__device__ __forceinline__ uint32_t smem_u32(const void* p) {
    uint32_t a;
    asm("{ .reg .u64 t; cvta.to.shared.u64 t, %1; cvt.u32.u64 %0, t; }" : "=r"(a) : "l"(p));
    return a;
}
__device__ __forceinline__ void cp16(uint32_t dst, const void* src) {
    asm volatile("cp.async.cg.shared.global [%0], [%1], 16;" :: "r"(dst), "l"(src));
}
#define SWZ(o) ((o) ^ (((o) >> 3) & 0x70))

__device__ __forceinline__ void ldsm4(uint32_t* r, uint32_t addr) {
    asm volatile("ldmatrix.sync.aligned.m8n8.x4.shared.b16 {%0,%1,%2,%3}, [%4];"
                 : "=r"(r[0]), "=r"(r[1]), "=r"(r[2]), "=r"(r[3]) : "r"(addr));
}
__device__ __forceinline__ void mma16816(float* c, const uint32_t* a, const uint32_t* b) {
    asm volatile(
        "mma.sync.aligned.m16n8k16.row.col.f32.f16.f16.f32 "
        "{%0,%1,%2,%3}, {%4,%5,%6,%7}, {%8,%9}, {%0,%1,%2,%3};"
        : "+f"(c[0]), "+f"(c[1]), "+f"(c[2]), "+f"(c[3])
        : "r"(a[0]), "r"(a[1]), "r"(a[2]), "r"(a[3]), "r"(b[0]), "r"(b[1]));
}

// ---------------- pack: Wp[c][k'] = fp16 split of g[k]*W[k][c] --------------
__global__ void __launch_bounds__(256) pack_kernel(const float* __restrict__ W,
    const float* __restrict__ g, __half* __restrict__ Wp, int C) {
    size_t total = (size_t)C * KTOT;
    for (size_t idx = (size_t)blockIdx.x * 256 + threadIdx.x; idx < total;
         idx += (size_t)gridDim.x * 256) {
        int c  = (int)(idx / KTOT);
        int kp = (int)(idx % KTOT);
        int k  = kp & 1023;
        float v = g[k] * W[(size_t)k * C + c];
        __half hi = __float2half(v);
        Wp[idx] = (kp < 1024) ? hi : __float2half(v - __half2float(hi));
    }
}

// gW[c] = sum_k g[k] W[k][c];  eW[c] = sum_k lnb[k] W[k][c] + bias[c]
__global__ void __launch_bounds__(256) gemv_kernel(const float* __restrict__ W,
    const float* __restrict__ g, const float* __restrict__ lnb,
    const float* __restrict__ bias, float* __restrict__ gW, float* __restrict__ eW, int C) {
    int c = blockIdx.x;
    float sg = 0.f, sb = 0.f;
    for (int k = threadIdx.x; k < KDIM; k += 256) {
        float w = W[(size_t)k * C + c];
        sg += g[k] * w; sb += lnb[k] * w;
    }
    __shared__ float ra[256], rb[256];
    ra[threadIdx.x] = sg; rb[threadIdx.x] = sb; __syncthreads();
    for (int o = 128; o > 0; o >>= 1) {
        if (threadIdx.x < o) { ra[threadIdx.x] += ra[threadIdx.x + o]; rb[threadIdx.x] += rb[threadIdx.x + o]; }
        __syncthreads();
    }
    if (threadIdx.x == 0) { gW[c] = ra[0]; eW[c] = rb[0] + bias[c]; }
}

// ---------------- stage 1: LN1 stats + fp16 round of concat(x) -------------
__global__ void __launch_bounds__(128) s1_kernel(
    const float* __restrict__ nodes, const float* __restrict__ aggr,
    const int* __restrict__ comps,
    __half* __restrict__ Aout, float* __restrict__ mu1, float* __restrict__ rs1,
    float* __restrict__ rsum, float* __restrict__ rsq, int n) {
    int row = blockIdx.x;
    if (row >= n) return;
    int t = threadIdx.x;
    const float4* p0 = (const float4*)(nodes + (size_t)row * FDIM);
    const float4* p1 = (const float4*)(aggr + (size_t)comps[row] * FDIM);
    float4 v0 = p0[t], v1 = p1[t];
    float s = v0.x + v0.y + v0.z + v0.w + v1.x + v1.y + v1.z + v1.w;
    float q = v0.x * v0.x + v0.y * v0.y + v0.z * v0.z + v0.w * v0.w
            + v1.x * v1.x + v1.y * v1.y + v1.z * v1.z + v1.w * v1.w;
#pragma unroll
    for (int o = 16; o > 0; o >>= 1) {
        s += __shfl_xor_sync(0xffffffffu, s, o);
        q += __shfl_xor_sync(0xffffffffu, q, o);
    }
    __shared__ float ss[4], qs[4];
    if ((t & 31) == 0) { ss[t >> 5] = s; qs[t >> 5] = q; }
    __syncthreads();
    if (t == 0) {
        s = ss[0] + ss[1] + ss[2] + ss[3];
        q = qs[0] + qs[1] + qs[2] + qs[3];
        float mu = s * (1.0f / 1024.0f);
        float var = q * (1.0f / 1024.0f) - mu * mu;
        mu1[row] = mu; rs1[row] = rsqrtf(var + 1e-5f);
        rsum[row] = 0.f; rsq[row] = 0.f;
    }
    __half2* base = (__half2*)(Aout + (size_t)row * 1024);
    base[2 * t + 0]   = __floats2half2_rn(v0.x, v0.y);
    base[2 * t + 1]   = __floats2half2_rn(v0.z, v0.w);
    base[256 + 2 * t] = __floats2half2_rn(v1.x, v1.y);
    base[257 + 2 * t] = __floats2half2_rn(v1.z, v1.w);
}

__global__ void __launch_bounds__(256) stat2_kernel(const float* __restrict__ rsum,
    const float* __restrict__ rsq, float* __restrict__ mu2, float* __restrict__ rs2, int n) {
    int i = blockIdx.x * 256 + threadIdx.x;
    if (i >= n) return;
    float mu = rsum[i] * (1.0f / 1024.0f);
    float var = rsq[i] * (1.0f / 1024.0f) - mu * mu;
    mu2[i] = mu; rs2[i] = rsqrtf(var + 1e-5f);
}

// ---------------- HMMA GEMM, K' = 2048, BM=BN=128, 8 warps -----------------
template <int LAYER>
__global__ void __launch_bounds__(256, 2) gemm_kernel(
    const __half* __restrict__ Ain, const __half* __restrict__ Bp,
    const float* __restrict__ mu, const float* __restrict__ rs,
    const float* __restrict__ gW, const float* __restrict__ eW,
    __half* __restrict__ Hout, float* __restrict__ outp,
    float* __restrict__ rsum, float* __restrict__ rsq, int n, int ncols)
{
    extern __shared__ char smem[];
    uint32_t sb = smem_u32(smem);
    const int tid  = threadIdx.x;
    const int wid  = tid >> 5;
    const int lane = tid & 31;
    const int wm = wid & 3, wn = wid >> 2;
    const int row0 = blockIdx.y * BM;
    const int col0 = blockIdx.x * BN;

    float acc[2][8][4];
#pragma unroll
    for (int mt = 0; mt < 2; mt++)
#pragma unroll
        for (int nt = 0; nt < 8; nt++)
#pragma unroll
            for (int i = 0; i < 4; i++) acc[mt][nt][i] = 0.f;

    auto load_chunk = [&](int c) {
        int st = c % STAGES;
        uint32_t abase = sb + st * STAGE_BYTES;
        uint32_t bbase = abase + TILE_BYTES;
        int acol = (c & 15) << 6;      // A repeats for both W halves
        int bcol = c << 6;
#pragma unroll
        for (int i = 0; i < 4; i++) {
            int v = tid + i * 256, r = v >> 3, cc = v & 7;
            int rg = row0 + r; if (rg >= n) rg = n - 1;
            cp16(abase + SWZ(r * 128 + cc * 16), Ain + (size_t)rg * 1024 + acol + cc * 8);
        }
#pragma unroll
        for (int i = 0; i < 4; i++) {
            int v = tid + i * 256, r = v >> 3, cc = v & 7;
            cp16(bbase + SWZ(r * 128 + cc * 16), Bp + (size_t)(col0 + r) * KTOT + bcol + cc * 8);
        }
        asm volatile("cp.async.commit_group;" ::: "memory");
    };

    load_chunk(0);
    load_chunk(1);

    const int a_row = wm * 32 + (lane & 15);
    const int b_row = wn * 64 + (lane & 15);
    const int k8    = (lane >> 4) * 8;

    for (int c = 0; c < NCHUNK; c++) {
        if (c + 2 < NCHUNK) asm volatile("cp.async.wait_group 1;" ::: "memory");
        else                asm volatile("cp.async.wait_group 0;" ::: "memory");
        __syncthreads();
        if (c + 2 < NCHUNK) load_chunk(c + 2);

        uint32_t abase = sb + (c % STAGES) * STAGE_BYTES;
        uint32_t bbase = abase + TILE_BYTES;
#pragma unroll
        for (int ks = 0; ks < 4; ks++) {
            uint32_t a[2][4], b[8][2];
#pragma unroll
            for (int mt = 0; mt < 2; mt++)
                ldsm4(a[mt], abase + SWZ((a_row + mt * 16) * 128 + (ks * 16 + k8) * 2));
#pragma unroll
            for (int nt16 = 0; nt16 < 4; nt16++) {
                uint32_t r[4];
                ldsm4(r, bbase + SWZ((b_row + nt16 * 16) * 128 + (ks * 16 + k8) * 2));
                b[2 * nt16 + 0][0] = r[0]; b[2 * nt16 + 0][1] = r[2];
                b[2 * nt16 + 1][0] = r[1]; b[2 * nt16 + 1][1] = r[3];
            }
#pragma unroll
            for (int mt = 0; mt < 2; mt++)
#pragma unroll
                for (int nt = 0; nt < 8; nt++)
                    mma16816(acc[mt][nt], a[mt], b[nt]);
        }
        __syncthreads();
    }

    // ---- epilogue ----
    const int qid   = lane >> 2;
    const int qlane = lane & 3;

    float gwv[8][2], ewv[8][2];
#pragma unroll
    for (int nt = 0; nt < 8; nt++) {
        int colb = col0 + wn * 64 + nt * 8 + qlane * 2;
        gwv[nt][0] = __ldg(gW + colb); gwv[nt][1] = __ldg(gW + colb + 1);
        ewv[nt][0] = __ldg(eW + colb); ewv[nt][1] = __ldg(eW + colb + 1);
    }

#pragma unroll
    for (int mt = 0; mt < 2; mt++) {
#pragma unroll
        for (int half = 0; half < 2; half++) {
            int row = row0 + wm * 32 + mt * 16 + qid + half * 8;
            bool valid = row < n;
            int rc = valid ? row : 0;
            float m_mu = mu[rc], m_rs = rs[rc];
            float ssum = 0.f, sq = 0.f;
#pragma unroll
            for (int nt = 0; nt < 8; nt++) {
                float c0 = m_rs * (acc[mt][nt][half * 2 + 0] - m_mu * gwv[nt][0]) + ewv[nt][0];
                float c1 = m_rs * (acc[mt][nt][half * 2 + 1] - m_mu * gwv[nt][1]) + ewv[nt][1];
                float h0 = c0 / (1.f + __expf(-c0));
                float h1 = c1 / (1.f + __expf(-c1));
                int colb = col0 + wn * 64 + nt * 8 + qlane * 2;
                if (LAYER == 1) {
                    ssum += h0 + h1; sq += h0 * h0 + h1 * h1;
                    if (valid)
                        *(__half2*)(Hout + (size_t)row * 1024 + colb) = __floats2half2_rn(h0, h1);
                } else {
                    if (valid) {
                        float2 v; v.x = h0; v.y = h1;
                        *(float2*)(outp + (size_t)row * ncols + colb) = v;
                    }
                }
            }
            if (LAYER == 1) {
                ssum += __shfl_xor_sync(0xffffffffu, ssum, 1);
                ssum += __shfl_xor_sync(0xffffffffu, ssum, 2);
                sq   += __shfl_xor_sync(0xffffffffu, sq, 1);
                sq   += __shfl_xor_sync(0xffffffffu, sq, 2);
                if (qlane == 0 && valid) {
                    atomicAdd(&rsum[row], ssum);
                    atomicAdd(&rsq[row], sq);
                }
            }
        }
    }
}

// ---------------------------------------------------------------------------
extern "C" void kernel_launch(void* const* d_in, const int* in_sizes, int n_in,
                              void* d_out, int out_size) {
    const float* nodes      = (const float*)d_in[1];
    const int*   comps      = (const int*)  d_in[2];
    const float* aggr_nodes = (const float*)d_in[4];
    const float* ln1_g      = (const float*)d_in[6];
    const float* ln1_b      = (const float*)d_in[7];
    const float* W1         = (const float*)d_in[8];
    const float* b1         = (const float*)d_in[9];
    const float* ln2_g      = (const float*)d_in[10];
    const float* ln2_b      = (const float*)d_in[11];
    const float* W2         = (const float*)d_in[12];
    const float* b2         = (const float*)d_in[13];
    float*       out        = (float*)d_out;

    const int n = in_sizes[1] / FDIM;

    __half *A, *H, *W1p, *W2p;
    float *gW1, *eW1, *gW2, *eW2, *mu1, *rs1, *mu2, *rs2, *rsum, *rsq;
    cudaGetSymbolAddress((void**)&A,    g_A);
    cudaGetSymbolAddress((void**)&H,    g_H);
    cudaGetSymbolAddress((void**)&W1p,  g_W1p);
    cudaGetSymbolAddress((void**)&W2p,  g_W2p);
    cudaGetSymbolAddress((void**)&gW1,  g_gW1);
    cudaGetSymbolAddress((void**)&eW1,  g_eW1);
    cudaGetSymbolAddress((void**)&gW2,  g_gW2);
    cudaGetSymbolAddress((void**)&eW2,  g_eW2);
    cudaGetSymbolAddress((void**)&mu1,  g_mu1);
    cudaGetSymbolAddress((void**)&rs1,  g_rs1);
    cudaGetSymbolAddress((void**)&mu2,  g_mu2);
    cudaGetSymbolAddress((void**)&rs2,  g_rs2);
    cudaGetSymbolAddress((void**)&rsum, g_rsum);
    cudaGetSymbolAddress((void**)&rsq,  g_rsq);

    cudaFuncSetAttribute(gemm_kernel<1>, cudaFuncAttributeMaxDynamicSharedMemorySize, SMEM_TOTAL);
    cudaFuncSetAttribute(gemm_kernel<2>, cudaFuncAttributeMaxDynamicSharedMemorySize, SMEM_TOTAL);

    const int rtiles = (n + BM - 1) / BM;

    // precompute (deterministic, every call)
    pack_kernel<<<2048, 256>>>(W1, ln1_g, W1p, KDIM);
    pack_kernel<<<1024, 256>>>(W2, ln2_g, W2p, FDIM);
    gemv_kernel<<<KDIM, 256>>>(W1, ln1_g, ln1_b, b1, gW1, eW1, KDIM);
    gemv_kernel<<<FDIM, 256>>>(W2, ln2_g, ln2_b, b2, gW2, eW2, FDIM);

    // stage 1: LN1 stats + fp16 round of concat(x)
    s1_kernel<<<n, 128>>>(nodes, aggr_nodes, comps, A, mu1, rs1, rsum, rsq, n);

    // GEMM1: h (fp16) + LN2 partial sums
    gemm_kernel<1><<<dim3(KDIM / BN, rtiles), 256, SMEM_TOTAL>>>(
        A, W1p, mu1, rs1, gW1, eW1, H, nullptr, rsum, rsq, n, KDIM);

    // LN2 stats
    stat2_kernel<<<(n + 255) / 256, 256>>>(rsum, rsq, mu2, rs2, n);

    // GEMM2 -> out
    gemm_kernel<2><<<dim3(FDIM / BN, rtiles), 256, SMEM_TOTAL>>>(
        H, W2p, mu2, rs2, gW2, eW2, nullptr, out, nullptr, nullptr, n, FDIM);
}